// round 1
// baseline (speedup 1.0000x reference)
#include <cuda_runtime.h>
#include <stdint.h>

// Problem constants (fixed shapes per reference)
#define NN 100000
#define EE 3200000
#define GG 1024
#define HH 16

// Scratch (device globals; no allocation allowed)
__device__ float d_h[NN * HH];     // scaled transform output hs = (x@W)*dis
__device__ float d_aggA[NN * HH];  // accumulators (raw sums)
__device__ float d_aggB[NN * HH];
__device__ float d_deg[NN];
__device__ float d_dis[NN];
__device__ float d_cnt[GG];

// ---------------------------------------------------------------------------
// K0: init deg=1 (self loop), cnt=0, out=bo
__global__ void k_init(float* __restrict__ out, const float* __restrict__ bo, int n, int g) {
    int i = blockIdx.x * blockDim.x + threadIdx.x;
    if (i < n) d_deg[i] = 1.0f;
    if (i < g) { d_cnt[i] = 0.0f; out[i] = bo[0]; }
}

// K1: degree count over dst + per-graph node count
__global__ void k_count(const int* __restrict__ dst, const int* __restrict__ batch,
                        int e, int n) {
    int i = blockIdx.x * blockDim.x + threadIdx.x;
    if (i < e) atomicAdd(&d_deg[dst[i]], 1.0f);
    if (i < n) atomicAdd(&d_cnt[batch[i]], 1.0f);
}

// K2: dis = rsqrt(deg)
__global__ void k_dis(int n) {
    int i = blockIdx.x * blockDim.x + threadIdx.x;
    if (i < n) d_dis[i] = rsqrtf(d_deg[i]);
}

// ---------------------------------------------------------------------------
// Layer 0 transform with fused embedding:
//   x = [W1[types]+b1, W2[pos]+b2]  (32)
//   hs = (x @ Wg0) * dis[n]         (16)
//   h_out[n] = hs ; agg_out[n] = hs (self-loop init)
__global__ void k_layer0(const int* __restrict__ types, const int* __restrict__ pos,
                         const float* __restrict__ W1, const float* __restrict__ b1,
                         const float* __restrict__ W2, const float* __restrict__ b2,
                         const float* __restrict__ Wg0,
                         float* __restrict__ h_out, float* __restrict__ agg_out, int n) {
    __shared__ float sW1[3 * HH], sb1[HH], sW2[3 * HH], sb2[HH], sW[32 * HH];
    int t = threadIdx.x;
    if (t < 48) sW1[t] = W1[t];
    if (t < 48) sW2[t] = W2[t];
    if (t < 16) { sb1[t] = b1[t]; sb2[t] = b2[t]; }
    for (int i = t; i < 32 * HH; i += blockDim.x) sW[i] = Wg0[i];
    __syncthreads();

    int nidx = blockIdx.x * blockDim.x + t;
    if (nidx >= n) return;

    int ty = types[nidx], pp = pos[nidx];
    float x[32];
#pragma unroll
    for (int j = 0; j < 16; j++) {
        x[j]      = sW1[ty * 16 + j] + sb1[j];
        x[16 + j] = sW2[pp * 16 + j] + sb2[j];
    }
    float acc[16];
#pragma unroll
    for (int j = 0; j < 16; j++) acc[j] = 0.0f;
#pragma unroll
    for (int i = 0; i < 32; i++) {
        float xi = x[i];
#pragma unroll
        for (int j = 0; j < 16; j++) acc[j] = fmaf(xi, sW[i * 16 + j], acc[j]);
    }
    float ds = d_dis[nidx];
    float4 v[4];
#pragma unroll
    for (int q = 0; q < 4; q++) {
        v[q].x = acc[q * 4 + 0] * ds;
        v[q].y = acc[q * 4 + 1] * ds;
        v[q].z = acc[q * 4 + 2] * ds;
        v[q].w = acc[q * 4 + 3] * ds;
    }
    float4* ho = (float4*)(h_out + (size_t)nidx * 16);
    float4* ao = (float4*)(agg_out + (size_t)nidx * 16);
#pragma unroll
    for (int q = 0; q < 4; q++) { ho[q] = v[q]; ao[q] = v[q]; }
}

// Mid-layer transform:
//   x = relu(dis[n]*agg_in[n] + b_prev)   (16)
//   hs = (x @ W) * dis[n]                 (16)
//   h_out = hs ; agg_out = hs
__global__ void k_layer(const float* __restrict__ agg_in,
                        const float* __restrict__ W, const float* __restrict__ b_prev,
                        float* __restrict__ h_out, float* __restrict__ agg_out, int n) {
    __shared__ float sW[16 * HH], sb[HH];
    int t = threadIdx.x;
    if (t < 16 * HH) sW[t] = W[t];
    if (t < HH) sb[t] = b_prev[t];
    __syncthreads();

    int nidx = blockIdx.x * blockDim.x + t;
    if (nidx >= n) return;

    float ds = d_dis[nidx];
    const float4* ai = (const float4*)(agg_in + (size_t)nidx * 16);
    float x[16];
#pragma unroll
    for (int q = 0; q < 4; q++) {
        float4 a = ai[q];
        x[q * 4 + 0] = fmaxf(fmaf(ds, a.x, sb[q * 4 + 0]), 0.0f);
        x[q * 4 + 1] = fmaxf(fmaf(ds, a.y, sb[q * 4 + 1]), 0.0f);
        x[q * 4 + 2] = fmaxf(fmaf(ds, a.z, sb[q * 4 + 2]), 0.0f);
        x[q * 4 + 3] = fmaxf(fmaf(ds, a.w, sb[q * 4 + 3]), 0.0f);
    }
    float acc[16];
#pragma unroll
    for (int j = 0; j < 16; j++) acc[j] = 0.0f;
#pragma unroll
    for (int i = 0; i < 16; i++) {
        float xi = x[i];
#pragma unroll
        for (int j = 0; j < 16; j++) acc[j] = fmaf(xi, sW[i * 16 + j], acc[j]);
    }
    float4* ho = (float4*)(h_out + (size_t)nidx * 16);
    float4* ao = (float4*)(agg_out + (size_t)nidx * 16);
#pragma unroll
    for (int q = 0; q < 4; q++) {
        float4 v;
        v.x = acc[q * 4 + 0] * ds; v.y = acc[q * 4 + 1] * ds;
        v.z = acc[q * 4 + 2] * ds; v.w = acc[q * 4 + 3] * ds;
        ho[q] = v; ao[q] = v;
    }
}

// ---------------------------------------------------------------------------
// Edge scatter: agg[dst] += h[src]   (raw sums; all coefficients pre-factored)
__device__ __forceinline__ void red_v4(float* p, float4 v) {
    asm volatile("red.global.add.v4.f32 [%0], {%1,%2,%3,%4};"
                 :: "l"(p), "f"(v.x), "f"(v.y), "f"(v.z), "f"(v.w) : "memory");
}

__global__ void k_scatter(const int* __restrict__ src, const int* __restrict__ dst,
                          const float* __restrict__ h, float* __restrict__ agg, int e) {
    int i = blockIdx.x * blockDim.x + threadIdx.x;
    if (i >= e) return;
    int s = src[i];
    int d = dst[i];
    const float4* hs = (const float4*)(h + (size_t)s * 16);
    float4 a0 = hs[0], a1 = hs[1], a2 = hs[2], a3 = hs[3];
    float* ap = agg + (size_t)d * 16;
    red_v4(ap + 0, a0);
    red_v4(ap + 4, a1);
    red_v4(ap + 8, a2);
    red_v4(ap + 12, a3);
}

// ---------------------------------------------------------------------------
// Pool: z = dis*agg + bg2 (no relu); s = dot(z, Wo); out[batch] += s/max(cnt,1)
__global__ void k_pool(const float* __restrict__ agg, const float* __restrict__ bg2,
                       const float* __restrict__ Wo, const int* __restrict__ batch,
                       float* __restrict__ out, int n) {
    __shared__ float sb[HH], sw[HH];
    int t = threadIdx.x;
    if (t < HH) { sb[t] = bg2[t]; sw[t] = Wo[t]; }
    __syncthreads();

    int nidx = blockIdx.x * blockDim.x + t;
    if (nidx >= n) return;

    float ds = d_dis[nidx];
    const float4* ai = (const float4*)(agg + (size_t)nidx * 16);
    float s = 0.0f;
#pragma unroll
    for (int q = 0; q < 4; q++) {
        float4 a = ai[q];
        s = fmaf(fmaf(ds, a.x, sb[q * 4 + 0]), sw[q * 4 + 0], s);
        s = fmaf(fmaf(ds, a.y, sb[q * 4 + 1]), sw[q * 4 + 1], s);
        s = fmaf(fmaf(ds, a.z, sb[q * 4 + 2]), sw[q * 4 + 2], s);
        s = fmaf(fmaf(ds, a.w, sb[q * 4 + 3]), sw[q * 4 + 3], s);
    }
    int g = batch[nidx];
    float c = fmaxf(d_cnt[g], 1.0f);
    atomicAdd(&out[g], s / c);
}

// ---------------------------------------------------------------------------
extern "C" void kernel_launch(void* const* d_in, const int* in_sizes, int n_in,
                              void* d_out, int out_size) {
    const int*   types = (const int*)d_in[0];
    const int*   pos   = (const int*)d_in[1];
    const int*   eidx  = (const int*)d_in[2];
    const int*   batch = (const int*)d_in[3];
    const float* W1  = (const float*)d_in[4];
    const float* b1  = (const float*)d_in[5];
    const float* W2  = (const float*)d_in[6];
    const float* b2  = (const float*)d_in[7];
    const float* Wg0 = (const float*)d_in[8];
    const float* bg0 = (const float*)d_in[9];
    const float* Wg1 = (const float*)d_in[10];
    const float* bg1 = (const float*)d_in[11];
    const float* Wg2 = (const float*)d_in[12];
    const float* bg2 = (const float*)d_in[13];
    const float* Wo  = (const float*)d_in[14];
    const float* bo  = (const float*)d_in[15];
    float* out = (float*)d_out;

    const int n = in_sizes[0];
    const int e = in_sizes[2] / 2;
    const int g = out_size;
    const int* src = eidx;
    const int* dst = eidx + e;

    float *hbuf, *aggA, *aggB;
    cudaGetSymbolAddress((void**)&hbuf, d_h);
    cudaGetSymbolAddress((void**)&aggA, d_aggA);
    cudaGetSymbolAddress((void**)&aggB, d_aggB);

    const int BT = 256;
    dim3 gN((n + BT - 1) / BT);
    dim3 gE((e + BT - 1) / BT);

    k_init<<<gN, BT>>>(out, bo, n, g);
    k_count<<<gE, BT>>>(dst, batch, e, n);
    k_dis<<<gN, BT>>>(n);

    // layer 0 (embed fused)
    k_layer0<<<gN, BT>>>(types, pos, W1, b1, W2, b2, Wg0, hbuf, aggA, n);
    k_scatter<<<gE, BT>>>(src, dst, hbuf, aggA, e);
    // layer 1
    k_layer<<<gN, BT>>>(aggA, Wg1, bg0, hbuf, aggB, n);
    k_scatter<<<gE, BT>>>(src, dst, hbuf, aggB, e);
    // layer 2
    k_layer<<<gN, BT>>>(aggB, Wg2, bg1, hbuf, aggA, n);
    k_scatter<<<gE, BT>>>(src, dst, hbuf, aggA, e);
    // pool + output
    k_pool<<<gN, BT>>>(aggA, bg2, Wo, batch, out, n);
}

// round 3
// speedup vs baseline: 2.0600x; 2.0600x over previous
#include <cuda_runtime.h>
#include <stdint.h>

#define NN 100000
#define EE 3200000
#define GG 1024
#define HH 16

// Scratch (device globals; no allocation allowed)
__device__ float d_h0[NN * HH];
__device__ float d_h1[NN * HH];
__device__ float d_dis[NN];
__device__ float d_cnt[GG];
__device__ int   d_edeg[NN];     // edge in-degree (no self loop)
__device__ int   d_row[NN];      // CSR row start
__device__ int   d_cursor[NN];   // fill cursor
__device__ int   d_csr[EE];      // src indices grouped by dst
__device__ int   d_bsum[1024];
__device__ int   d_bbase[1024];

// ---------------------------------------------------------------------------
__global__ void k_init(float* __restrict__ out, const float* __restrict__ bo, int n, int g) {
    int i = blockIdx.x * blockDim.x + threadIdx.x;
    if (i < n) d_edeg[i] = 0;
    if (i < g) { d_cnt[i] = 0.0f; out[i] = bo[0]; }
}

__global__ void k_count(const int* __restrict__ dst, const int* __restrict__ batch,
                        int e, int n) {
    int i = blockIdx.x * blockDim.x + threadIdx.x;
    if (i < e) atomicAdd(&d_edeg[dst[i]], 1);
    if (i < n) atomicAdd(&d_cnt[batch[i]], 1.0f);
}

__global__ void k_dis(int n) {
    int i = blockIdx.x * blockDim.x + threadIdx.x;
    if (i < n) d_dis[i] = rsqrtf((float)d_edeg[i] + 1.0f);
}

// ---- 3-pass exclusive scan of d_edeg -> d_row / d_cursor --------------------
#define SCAN_T 1024
__global__ void k_block_sums(int n) {
    __shared__ int sh[SCAN_T];
    int i = blockIdx.x * SCAN_T + threadIdx.x;
    sh[threadIdx.x] = (i < n) ? d_edeg[i] : 0;
    __syncthreads();
    for (int off = SCAN_T / 2; off > 0; off >>= 1) {
        if (threadIdx.x < off) sh[threadIdx.x] += sh[threadIdx.x + off];
        __syncthreads();
    }
    if (threadIdx.x == 0) d_bsum[blockIdx.x] = sh[0];
}

__global__ void k_scan_bsum(int nb) {
    __shared__ int sh[SCAN_T];
    int v = (threadIdx.x < nb) ? d_bsum[threadIdx.x] : 0;
    sh[threadIdx.x] = v;
    __syncthreads();
    for (int off = 1; off < SCAN_T; off <<= 1) {
        int t = (threadIdx.x >= off) ? sh[threadIdx.x - off] : 0;
        __syncthreads();
        sh[threadIdx.x] += t;
        __syncthreads();
    }
    if (threadIdx.x < nb) d_bbase[threadIdx.x] = sh[threadIdx.x] - v;
}

__global__ void k_scan_local(int n) {
    __shared__ int sh[SCAN_T];
    int i = blockIdx.x * SCAN_T + threadIdx.x;
    int v = (i < n) ? d_edeg[i] : 0;
    sh[threadIdx.x] = v;
    __syncthreads();
    for (int off = 1; off < SCAN_T; off <<= 1) {
        int t = (threadIdx.x >= off) ? sh[threadIdx.x - off] : 0;
        __syncthreads();
        sh[threadIdx.x] += t;
        __syncthreads();
    }
    if (i < n) {
        int excl = sh[threadIdx.x] - v + d_bbase[blockIdx.x];
        d_row[i] = excl;
        d_cursor[i] = excl;
    }
}

__global__ void k_fill(const int* __restrict__ src, const int* __restrict__ dst, int e) {
    int i = blockIdx.x * blockDim.x + threadIdx.x;
    if (i >= e) return;
    int d = dst[i];
    int p = atomicAdd(&d_cursor[d], 1);
    d_csr[p] = src[i];
}

// ---------------------------------------------------------------------------
// Layer 0: embed + (x @ Wg0) * dis -> h0   (one thread per node)
__global__ void k_layer0(const int* __restrict__ types, const int* __restrict__ pos,
                         const float* __restrict__ W1, const float* __restrict__ b1,
                         const float* __restrict__ W2, const float* __restrict__ b2,
                         const float* __restrict__ Wg0,
                         float* __restrict__ h_out, int n) {
    __shared__ float sW1[3 * HH], sb1[HH], sW2[3 * HH], sb2[HH], sW[32 * HH];
    int t = threadIdx.x;
    if (t < 48) { sW1[t] = W1[t]; sW2[t] = W2[t]; }
    if (t < 16) { sb1[t] = b1[t]; sb2[t] = b2[t]; }
    for (int i = t; i < 32 * HH; i += blockDim.x) sW[i] = Wg0[i];
    __syncthreads();

    int nidx = blockIdx.x * blockDim.x + t;
    if (nidx >= n) return;

    int ty = types[nidx], pp = pos[nidx];
    float x[32];
#pragma unroll
    for (int j = 0; j < 16; j++) {
        x[j]      = sW1[ty * 16 + j] + sb1[j];
        x[16 + j] = sW2[pp * 16 + j] + sb2[j];
    }
    float acc[16];
#pragma unroll
    for (int j = 0; j < 16; j++) acc[j] = 0.0f;
#pragma unroll
    for (int i = 0; i < 32; i++) {
        float xi = x[i];
#pragma unroll
        for (int j = 0; j < 16; j++) acc[j] = fmaf(xi, sW[i * 16 + j], acc[j]);
    }
    float ds = d_dis[nidx];
    float4* ho = (float4*)(h_out + (size_t)nidx * 16);
#pragma unroll
    for (int q = 0; q < 4; q++) {
        float4 v;
        v.x = acc[q * 4 + 0] * ds; v.y = acc[q * 4 + 1] * ds;
        v.z = acc[q * 4 + 2] * ds; v.w = acc[q * 4 + 3] * ds;
        ho[q] = v;
    }
}

// ---------------------------------------------------------------------------
// Aggregate (CSR gather) + transform. One 4-thread quad per node; each thread
// owns 4 feature channels (a float4). No atomics. All intra-loop shuffles use
// the per-quad mask (the 4 quad lanes are always converged).
__global__ void k_agg_layer(const float* __restrict__ h_in,
                            const float* __restrict__ W, const float* __restrict__ b_prev,
                            float* __restrict__ h_out, int n) {
    __shared__ float sW[16 * HH], sb[HH];
    int t = threadIdx.x;
    if (t < 16 * HH) sW[t] = W[t];
    if (t < HH) sb[t] = b_prev[t];
    __syncthreads();

    int node_raw = (blockIdx.x * blockDim.x + t) >> 2;
    bool valid = node_raw < n;
    int node = valid ? node_raw : (n - 1);
    int q = t & 3;
    unsigned qmask = 0xFu << ((t & 31) & ~3);

    int base = d_row[node];
    int deg  = d_edeg[node];

    float4 sum = *((const float4*)(h_in + (size_t)node * 16) + q);  // self

    int j = 0;
    for (; j + 4 <= deg; j += 4) {
        int myidx = d_csr[base + j + q];
#pragma unroll
        for (int r = 0; r < 4; r++) {
            int id = __shfl_sync(qmask, myidx, r, 4);
            float4 v = *((const float4*)(h_in + (size_t)id * 16) + q);
            sum.x += v.x; sum.y += v.y; sum.z += v.z; sum.w += v.w;
        }
    }
    for (; j < deg; j++) {
        int id = d_csr[base + j];
        float4 v = *((const float4*)(h_in + (size_t)id * 16) + q);
        sum.x += v.x; sum.y += v.y; sum.z += v.z; sum.w += v.w;
    }

    float ds = d_dis[node];
    float x0 = fmaxf(fmaf(ds, sum.x, sb[q * 4 + 0]), 0.0f);
    float x1 = fmaxf(fmaf(ds, sum.y, sb[q * 4 + 1]), 0.0f);
    float x2 = fmaxf(fmaf(ds, sum.z, sb[q * 4 + 2]), 0.0f);
    float x3 = fmaxf(fmaf(ds, sum.w, sb[q * 4 + 3]), 0.0f);

    float acc0 = 0.f, acc1 = 0.f, acc2 = 0.f, acc3 = 0.f;
#pragma unroll
    for (int r = 0; r < 4; r++) {
        float y0 = __shfl_sync(qmask, x0, r, 4);
        float y1 = __shfl_sync(qmask, x1, r, 4);
        float y2 = __shfl_sync(qmask, x2, r, 4);
        float y3 = __shfl_sync(qmask, x3, r, 4);
        int i0 = r * 4;
        const float* w0 = &sW[(i0 + 0) * 16 + q * 4];
        const float* w1 = &sW[(i0 + 1) * 16 + q * 4];
        const float* w2 = &sW[(i0 + 2) * 16 + q * 4];
        const float* w3 = &sW[(i0 + 3) * 16 + q * 4];
        acc0 = fmaf(y0, w0[0], fmaf(y1, w1[0], fmaf(y2, w2[0], fmaf(y3, w3[0], acc0))));
        acc1 = fmaf(y0, w0[1], fmaf(y1, w1[1], fmaf(y2, w2[1], fmaf(y3, w3[1], acc1))));
        acc2 = fmaf(y0, w0[2], fmaf(y1, w1[2], fmaf(y2, w2[2], fmaf(y3, w3[2], acc2))));
        acc3 = fmaf(y0, w0[3], fmaf(y1, w1[3], fmaf(y2, w2[3], fmaf(y3, w3[3], acc3))));
    }

    if (valid) {
        float4 o;
        o.x = acc0 * ds; o.y = acc1 * ds; o.z = acc2 * ds; o.w = acc3 * ds;
        *((float4*)(h_out + (size_t)node * 16) + q) = o;
    }
}

// Last layer: aggregate + (dis*sum + bg2) . Wo, mean-pool into out[batch].
__global__ void k_agg_pool(const float* __restrict__ h_in,
                           const float* __restrict__ bg2, const float* __restrict__ Wo,
                           const int* __restrict__ batch, float* __restrict__ out, int n) {
    __shared__ float sb[HH], sw[HH];
    int t = threadIdx.x;
    if (t < HH) { sb[t] = bg2[t]; sw[t] = Wo[t]; }
    __syncthreads();

    int node_raw = (blockIdx.x * blockDim.x + t) >> 2;
    bool valid = node_raw < n;
    int node = valid ? node_raw : (n - 1);
    int q = t & 3;
    unsigned qmask = 0xFu << ((t & 31) & ~3);

    int base = d_row[node];
    int deg  = d_edeg[node];

    float4 sum = *((const float4*)(h_in + (size_t)node * 16) + q);

    int j = 0;
    for (; j + 4 <= deg; j += 4) {
        int myidx = d_csr[base + j + q];
#pragma unroll
        for (int r = 0; r < 4; r++) {
            int id = __shfl_sync(qmask, myidx, r, 4);
            float4 v = *((const float4*)(h_in + (size_t)id * 16) + q);
            sum.x += v.x; sum.y += v.y; sum.z += v.z; sum.w += v.w;
        }
    }
    for (; j < deg; j++) {
        int id = d_csr[base + j];
        float4 v = *((const float4*)(h_in + (size_t)id * 16) + q);
        sum.x += v.x; sum.y += v.y; sum.z += v.z; sum.w += v.w;
    }

    float ds = d_dis[node];
    float p = fmaf(ds, sum.x, sb[q * 4 + 0]) * sw[q * 4 + 0]
            + fmaf(ds, sum.y, sb[q * 4 + 1]) * sw[q * 4 + 1]
            + fmaf(ds, sum.z, sb[q * 4 + 2]) * sw[q * 4 + 2]
            + fmaf(ds, sum.w, sb[q * 4 + 3]) * sw[q * 4 + 3];
    // reduce across quad (quad lanes converged)
    p += __shfl_xor_sync(qmask, p, 1, 4);
    p += __shfl_xor_sync(qmask, p, 2, 4);

    // Full warp is reconverged from here on (no early returns above).
    int g = batch[node];
    float c = fmaxf(d_cnt[g], 1.0f);
    float contrib = (q == 0 && valid) ? p / c : 0.0f;

    // batch is sorted: most warps hold nodes of a single graph -> one atomic
    int g0 = __shfl_sync(0xffffffffu, g, 0);
    bool uni = __all_sync(0xffffffffu, g == g0);
    if (uni) {
#pragma unroll
        for (int off = 16; off > 0; off >>= 1)
            contrib += __shfl_xor_sync(0xffffffffu, contrib, off);
        if ((t & 31) == 0) atomicAdd(&out[g0], contrib);
    } else {
        if (q == 0 && valid) atomicAdd(&out[g], contrib);
    }
}

// ---------------------------------------------------------------------------
extern "C" void kernel_launch(void* const* d_in, const int* in_sizes, int n_in,
                              void* d_out, int out_size) {
    const int*   types = (const int*)d_in[0];
    const int*   pos   = (const int*)d_in[1];
    const int*   eidx  = (const int*)d_in[2];
    const int*   batch = (const int*)d_in[3];
    const float* W1  = (const float*)d_in[4];
    const float* b1  = (const float*)d_in[5];
    const float* W2  = (const float*)d_in[6];
    const float* b2  = (const float*)d_in[7];
    const float* Wg0 = (const float*)d_in[8];
    const float* bg0 = (const float*)d_in[9];
    const float* Wg1 = (const float*)d_in[10];
    const float* bg1 = (const float*)d_in[11];
    const float* Wg2 = (const float*)d_in[12];
    const float* bg2 = (const float*)d_in[13];
    const float* Wo  = (const float*)d_in[14];
    const float* bo  = (const float*)d_in[15];
    float* out = (float*)d_out;

    const int n = in_sizes[0];
    const int e = in_sizes[2] / 2;
    const int g = out_size;
    const int* src = eidx;
    const int* dst = eidx + e;

    float *h0, *h1;
    cudaGetSymbolAddress((void**)&h0, d_h0);
    cudaGetSymbolAddress((void**)&h1, d_h1);

    const int BT = 256;
    dim3 gN((n + BT - 1) / BT);
    dim3 gE((e + BT - 1) / BT);
    dim3 gQ(((n * 4) + BT - 1) / BT);    // quad-per-node kernels
    int nb = (n + SCAN_T - 1) / SCAN_T;  // scan blocks (98 for N=100000)

    k_init<<<gN, BT>>>(out, bo, n, g);
    k_count<<<gE, BT>>>(dst, batch, e, n);
    k_dis<<<gN, BT>>>(n);

    // CSR build
    k_block_sums<<<nb, SCAN_T>>>(n);
    k_scan_bsum<<<1, SCAN_T>>>(nb);
    k_scan_local<<<nb, SCAN_T>>>(n);
    k_fill<<<gE, BT>>>(src, dst, e);

    // layer 0 (embed fused)
    k_layer0<<<gN, BT>>>(types, pos, W1, b1, W2, b2, Wg0, h0, n);
    // layers 1,2 fused agg+transform
    k_agg_layer<<<gQ, BT>>>(h0, Wg1, bg0, h1, n);
    k_agg_layer<<<gQ, BT>>>(h1, Wg2, bg1, h0, n);
    // last aggregation fused with pool
    k_agg_pool<<<gQ, BT>>>(h0, bg2, Wo, batch, out, n);
}